// round 3
// baseline (speedup 1.0000x reference)
#include <cuda_runtime.h>
#include <math.h>

#define NB    2
#define NC    128
#define NH    512
#define NW    512
#define NWIN  4096      // 64 x 64 windows
#define NWF   1228      // int(4096 * 0.3)
#define NSEL  (NB*NWF)  // 2456
#define WINSZ 64
#define SCALE 0.08838834764831845f   // 128^-0.5

// ---------------- scratch (static device globals; allocation-free) ----------
__device__ float g_score[NB*NWIN];
__device__ int   g_sel[NB*NWF];
__device__ int   g_cnt[NB];
__device__ float g_gx[NB*NC*64];          // pooled features [b][c][cell]
__device__ float g_kv[2*NB*64*NC];        // k then v: [b][p][c]

// ---------------- window scores (double accumulation, rounded to fp32) -----
__global__ void scores_kernel(const float* __restrict__ unc) {
    if (blockIdx.x == 0 && threadIdx.x < NB) g_cnt[threadIdx.x] = 0;
    int gw   = blockIdx.x * 8 + (threadIdx.x >> 5);
    int lane = threadIdx.x & 31;
    if (gw >= NB*NWIN) return;
    int b = gw / NWIN, w = gw % NWIN;
    int wh = w >> 6, ww = w & 63;
    const float* base = unc + ((size_t)b*NH + wh*8)*NW + ww*8;
    int r0 = lane >> 3, c0 = lane & 7;
    double s = (double)base[r0*NW + c0] + (double)base[(r0+4)*NW + c0];
    #pragma unroll
    for (int o = 16; o; o >>= 1) s += __shfl_down_sync(0xffffffffu, s, o);
    if (lane == 0) g_score[gw] = (float)(s * (1.0/64.0));
}

// ---------------- stable top-k via rank (score desc, index asc) ------------
__global__ void select_kernel() {
    __shared__ float s_sc[NWIN];
    int b = blockIdx.x >> 2;
    int part = blockIdx.x & 3;
    const float* sc = g_score + b*NWIN;
    for (int i = threadIdx.x; i < NWIN; i += 1024) s_sc[i] = sc[i];
    __syncthreads();
    int w = part*1024 + threadIdx.x;
    float my = s_sc[w];
    int rank = 0;
    #pragma unroll 8
    for (int j = 0; j < NWIN; j++) {
        float v = s_sc[j];
        rank += (v > my) || (v == my && j < w);
    }
    if (rank < NWF) {
        int pos = atomicAdd(&g_cnt[b], 1);
        g_sel[b*NWF + pos] = w;
    }
}

// ---------------- 8x8 grid avg-pool (each cell = 64x64 block mean) ---------
__global__ void pool_kernel(const float* __restrict__ fm) {
    __shared__ float sp[512];
    int bci = blockIdx.x;          // (b*NC + c)*8 + ci
    int ci  = bci & 7;
    int bc  = bci >> 3;
    const float* base = fm + ((size_t)bc*NH + ci*64)*NW;
    int t = threadIdx.x;
    float acc = 0.f;
    #pragma unroll 4
    for (int r = 0; r < 64; r++) acc += base[(size_t)r*NW + t];
    sp[t] = acc;
    __syncthreads();
    for (int off = 32; off >= 1; off >>= 1) {
        if ((t & 63) < off) sp[t] += sp[t + off];
        __syncthreads();
    }
    if ((t & 63) == 0) {
        int cell = ci*8 + (t >> 6);
        g_gx[bc*64 + cell] = sp[t] * (1.0f/4096.0f);
    }
}

// ---------------- k,v = pooled @ kv_g_w^T -----------------------------------
__global__ void kv_kernel(const float* __restrict__ kvw) {
    __shared__ float sg[NC];
    int b = blockIdx.x >> 6;
    int p = blockIdx.x & 63;
    int c = threadIdx.x;
    sg[c] = g_gx[(b*NC + c)*64 + p];
    __syncthreads();
    float ka = 0.f, va = 0.f;
    #pragma unroll 8
    for (int cc = 0; cc < NC; cc++) {
        float g = sg[cc];
        ka = fmaf(g, kvw[c*NC + cc],        ka);
        va = fmaf(g, kvw[(c+NC)*NC + cc],   va);
    }
    g_kv[((size_t)b*64 + p)*NC + c]                 = ka;
    g_kv[(size_t)NB*64*NC + ((size_t)b*64 + p)*NC + c] = va;
}

// ---------------- fused per-window kernel -----------------------------------
// shared layout (floats): wf[64][129], x[64][129], y[64][129], attn[64][65], wt[32][129]
#define SM_WF   0
#define SM_X    (64*129)
#define SM_Y    (2*64*129)
#define SM_ATTN (3*64*129)
#define SM_WT   (3*64*129 + 64*65)
#define SM_FLOATS (3*64*129 + 64*65 + 32*129)
#define SM_BYTES  (SM_FLOATS*4)

__device__ __forceinline__ float gelu_exact(float x) {
    return 0.5f * x * (1.0f + erff(x * 0.70710678118654752f));
}

// out[64][128] = in[64][128] @ W^T (+bias), W row-major [128][128]
__device__ __forceinline__ void gemm128(const float (*in)[129], const float* __restrict__ W,
                                        const float* __restrict__ bias,
                                        float (*out)[129], float (*s_wt)[129],
                                        int wp, int lane) {
    float acc[8][4];
    #pragma unroll
    for (int j = 0; j < 8; j++)
        #pragma unroll
        for (int k = 0; k < 4; k++) acc[j][k] = 0.f;

    for (int cc0 = 0; cc0 < 128; cc0 += 32) {
        __syncthreads();
        #pragma unroll
        for (int k = 0; k < 16; k++) {
            int c = wp + 8*k;
            s_wt[lane][c] = W[c*128 + cc0 + lane];
        }
        __syncthreads();
        #pragma unroll
        for (int q = 0; q < 32; q++) {
            float a[8], bb[4];
            #pragma unroll
            for (int j = 0; j < 8; j++) a[j] = in[8*wp + j][cc0 + q];
            #pragma unroll
            for (int k = 0; k < 4; k++) bb[k] = s_wt[q][lane + 32*k];
            #pragma unroll
            for (int j = 0; j < 8; j++)
                #pragma unroll
                for (int k = 0; k < 4; k++)
                    acc[j][k] = fmaf(a[j], bb[k], acc[j][k]);
        }
    }
    float bv[4] = {0.f, 0.f, 0.f, 0.f};
    if (bias) {
        #pragma unroll
        for (int k = 0; k < 4; k++) bv[k] = bias[lane + 32*k];
    }
    #pragma unroll
    for (int j = 0; j < 8; j++)
        #pragma unroll
        for (int k = 0; k < 4; k++)
            out[8*wp + j][lane + 32*k] = acc[j][k] + bv[k];
}

// out[64][128] = attn[64][64] @ v[64][128]   (all in shared; caller syncs)
__device__ __forceinline__ void gemm_av(const float (*attn)[65], const float (*v)[129],
                                        float (*out)[129], int wp, int lane) {
    float acc[8][4];
    #pragma unroll
    for (int j = 0; j < 8; j++)
        #pragma unroll
        for (int k = 0; k < 4; k++) acc[j][k] = 0.f;
    #pragma unroll 4
    for (int j = 0; j < 64; j++) {
        float a[8], bb[4];
        #pragma unroll
        for (int ji = 0; ji < 8; ji++) a[ji] = attn[8*wp + ji][j];
        #pragma unroll
        for (int k = 0; k < 4; k++) bb[k] = v[j][lane + 32*k];
        #pragma unroll
        for (int ji = 0; ji < 8; ji++)
            #pragma unroll
            for (int k = 0; k < 4; k++)
                acc[ji][k] = fmaf(a[ji], bb[k], acc[ji][k]);
    }
    #pragma unroll
    for (int ji = 0; ji < 8; ji++)
        #pragma unroll
        for (int k = 0; k < 4; k++)
            out[8*wp + ji][lane + 32*k] = acc[ji][k];
}

// attn[64][64] = SCALE * q[64][128] @ k[64][128]^T   (caller syncs)
__device__ __forceinline__ void scores_qk(const float (*q)[129], const float (*k)[129],
                                          float (*attn)[65], int wp, int lane) {
    float acc[8][2];
    #pragma unroll
    for (int j = 0; j < 8; j++) { acc[j][0] = 0.f; acc[j][1] = 0.f; }
    #pragma unroll 4
    for (int c = 0; c < 128; c++) {
        float b0 = k[lane][c], b1 = k[lane + 32][c];
        #pragma unroll
        for (int j = 0; j < 8; j++) {
            float a = q[8*wp + j][c];
            acc[j][0] = fmaf(a, b0, acc[j][0]);
            acc[j][1] = fmaf(a, b1, acc[j][1]);
        }
    }
    #pragma unroll
    for (int j = 0; j < 8; j++) {
        attn[8*wp + j][lane]      = acc[j][0] * SCALE;
        attn[8*wp + j][lane + 32] = acc[j][1] * SCALE;
    }
}

// row-wise softmax over [64][64]; 4 threads per row (caller syncs before/after)
__device__ __forceinline__ void softmax64(float (*attn)[65], int tid) {
    int row = tid >> 2, q = tid & 3;
    float m = -1e30f;
    #pragma unroll
    for (int k = 0; k < 16; k++) m = fmaxf(m, attn[row][q*16 + k]);
    m = fmaxf(m, __shfl_xor_sync(0xffffffffu, m, 1));
    m = fmaxf(m, __shfl_xor_sync(0xffffffffu, m, 2));
    float s = 0.f;
    #pragma unroll
    for (int k = 0; k < 16; k++) {
        float e = expf(attn[row][q*16 + k] - m);
        attn[row][q*16 + k] = e;
        s += e;
    }
    s += __shfl_xor_sync(0xffffffffu, s, 1);
    s += __shfl_xor_sync(0xffffffffu, s, 2);
    float inv = 1.0f / s;
    #pragma unroll
    for (int k = 0; k < 16; k++) attn[row][q*16 + k] *= inv;
}

__global__ void __launch_bounds__(256, 1) window_kernel(
    const float* __restrict__ fm,
    const float* __restrict__ qgw,
    const float* __restrict__ lw, const float* __restrict__ lb,
    const float* __restrict__ qkvw,
    const float* __restrict__ pw, const float* __restrict__ pb,
    float* __restrict__ out)
{
    extern __shared__ float sm[];
    float (*s_wf)[129]  = (float (*)[129])(sm + SM_WF);
    float (*s_x)[129]   = (float (*)[129])(sm + SM_X);
    float (*s_y)[129]   = (float (*)[129])(sm + SM_Y);
    float (*s_attn)[65] = (float (*)[65]) (sm + SM_ATTN);
    float (*s_wt)[129]  = (float (*)[129])(sm + SM_WT);

    int tid = threadIdx.x, wp = tid >> 5, lane = tid & 31;
    int n = blockIdx.x;
    int b = n / NWF;
    int w = g_sel[n];
    int wh = w >> 6, ww = w & 63;
    const size_t plane = (size_t)NH * NW;
    const float* fbase = fm + (size_t)b*NC*plane + (size_t)(wh*8)*NW + ww*8;
    float*       obase = out + (size_t)b*NC*plane + (size_t)(wh*8)*NW + ww*8;

    // ---- gather window: s_wf[r*8+col][c] ----
    {
        int col = tid & 7, r = (tid >> 3) & 7, c0 = tid >> 6;
        #pragma unroll
        for (int k = 0; k < 32; k++) {
            int c = c0 + 4*k;
            s_wf[r*8 + col][c] = fbase[(size_t)c*plane + r*NW + col];
        }
    }

    // ---- cross attention vs pooled k/v ----
    gemm128(s_wf, qgw, nullptr, s_x, s_wt, wp, lane);          // q
    __syncthreads();
    {
        const float* kb = g_kv + (size_t)(b*64)*NC;
        #pragma unroll
        for (int k = 0; k < 32; k++) { int idx = tid + 256*k; s_y[idx >> 7][idx & 127] = kb[idx]; }
    }
    __syncthreads();
    scores_qk(s_x, s_y, s_attn, wp, lane);
    __syncthreads();
    softmax64(s_attn, tid);
    __syncthreads();
    {
        const float* vb = g_kv + (size_t)NB*64*NC + (size_t)(b*64)*NC;
        #pragma unroll
        for (int k = 0; k < 32; k++) { int idx = tid + 256*k; s_y[idx >> 7][idx & 127] = vb[idx]; }
    }
    __syncthreads();
    gemm_av(s_attn, s_y, s_x, wp, lane);
    __syncthreads();
    #pragma unroll
    for (int k = 0; k < 32; k++) {
        int idx = tid + 256*k;
        s_wf[idx >> 7][idx & 127] += s_x[idx >> 7][idx & 127];
    }

    // ---- MLP 1: wf += gelu(wf @ linner0^T + b) ----
    gemm128(s_wf, lw, lb, s_x, s_wt, wp, lane);
    __syncthreads();
    #pragma unroll
    for (int k = 0; k < 32; k++) {
        int idx = tid + 256*k;
        s_wf[idx >> 7][idx & 127] += gelu_exact(s_x[idx >> 7][idx & 127]);
    }

    // ---- window self-attention ----
    gemm128(s_wf, qkvw,            nullptr, s_x, s_wt, wp, lane);  // q2
    gemm128(s_wf, qkvw + 128*128,  nullptr, s_y, s_wt, wp, lane);  // k2
    __syncthreads();
    scores_qk(s_x, s_y, s_attn, wp, lane);
    __syncthreads();
    softmax64(s_attn, tid);
    gemm128(s_wf, qkvw + 256*128,  nullptr, s_x, s_wt, wp, lane);  // v2 (leading sync inside)
    __syncthreads();
    gemm_av(s_attn, s_x, s_y, wp, lane);                           // av -> s_y
    __syncthreads();
    // scrambled residual from reference's swapaxes+reshape:
    // wf[i][j] += av[j%64][2*i + j/64]
    #pragma unroll
    for (int k = 0; k < 32; k++) {
        int idx = tid + 256*k;
        int i = idx >> 7, j = idx & 127;
        s_wf[i][j] += s_y[j & 63][2*i + (j >> 6)];
    }

    // ---- MLP 2: wf += gelu(wf @ proj^T + b) ----
    gemm128(s_wf, pw, pb, s_x, s_wt, wp, lane);
    __syncthreads();
    #pragma unroll
    for (int k = 0; k < 32; k++) {
        int idx = tid + 256*k;
        s_wf[idx >> 7][idx & 127] += gelu_exact(s_x[idx >> 7][idx & 127]);
    }
    __syncthreads();

    // ---- scatter back ----
    {
        int col = tid & 7, r = (tid >> 3) & 7, c0 = tid >> 6;
        #pragma unroll
        for (int k = 0; k < 32; k++) {
            int c = c0 + 4*k;
            obase[(size_t)c*plane + r*NW + col] = s_wf[r*8 + col][c];
        }
    }
}

// ---------------- launch -----------------------------------------------------
extern "C" void kernel_launch(void* const* d_in, const int* in_sizes, int n_in,
                              void* d_out, int out_size) {
    const float* fm   = (const float*)d_in[0];
    const float* unc  = (const float*)d_in[1];
    const float* qgw  = (const float*)d_in[2];
    const float* kvw  = (const float*)d_in[3];
    const float* lw   = (const float*)d_in[4];
    const float* lb   = (const float*)d_in[5];
    const float* qkvw = (const float*)d_in[6];
    const float* pw   = (const float*)d_in[7];
    const float* pb   = (const float*)d_in[8];
    float* out = (float*)d_out;

    cudaFuncSetAttribute(window_kernel,
                         cudaFuncAttributeMaxDynamicSharedMemorySize, SM_BYTES);

    // output starts as a copy of the input feature map
    cudaMemcpyAsync(out, fm, sizeof(float)*(size_t)NB*NC*NH*NW,
                    cudaMemcpyDeviceToDevice, 0);

    scores_kernel<<<1024, 256>>>(unc);
    select_kernel<<<8, 1024>>>();
    pool_kernel<<<NB*NC*8, 512>>>(fm);
    kv_kernel<<<NB*64, 128>>>(kvw);
    window_kernel<<<NSEL, 256, SM_BYTES>>>(fm, qgw, lw, lb, qkvw, pw, pb, out);
}